// round 14
// baseline (speedup 1.0000x reference)
#include <cuda_runtime.h>
#include <math.h>
#include <stdint.h>

#define BWIN   2048
#define NTOK   64
#define CDIM   256
#define MROWS  (BWIN * NTOK)
#define NBATCH 32
#define SCALE  0.0625f

// ---------------- scratch ----------------------------------------------------
__device__ float g_bias[NBATCH * NTOK * NTOK];
__device__ float g_Wc[512 * CDIM];    // tf32 bits: rows 0-255 = M, 256-511 = Wz
__device__ float g_wv[CDIM];          // sum_i Wk[i,c]*bq[i]
__device__ float g_d [CDIM];          // Wp@bv + bp
__device__ float g_G1[MROWS * CDIM];  // tf32
__device__ float g_Z [MROWS * CDIM];  // tf32

// ---------------- helpers -----------------------------------------------------
__device__ __forceinline__ uint32_t f2tf(float f) {
    uint32_t u; asm("cvt.rna.tf32.f32 %0, %1;" : "=r"(u) : "f"(f)); return u;
}
__device__ __forceinline__ uint32_t u2tf(uint32_t x) {
    uint32_t u; asm("cvt.rna.tf32.f32 %0, %1;" : "=r"(u) : "f"(__uint_as_float(x))); return u;
}
__device__ __forceinline__ void mma8(float* c, uint32_t a0, uint32_t a1, uint32_t a2, uint32_t a3,
                                     uint32_t b0, uint32_t b1) {
    asm volatile(
        "mma.sync.aligned.m16n8k8.row.col.f32.tf32.tf32.f32 "
        "{%0,%1,%2,%3},{%4,%5,%6,%7},{%8,%9},{%0,%1,%2,%3};"
        : "+f"(c[0]), "+f"(c[1]), "+f"(c[2]), "+f"(c[3])
        : "r"(a0), "r"(a1), "r"(a2), "r"(a3), "r"(b0), "r"(b1));
}
__device__ __forceinline__ void ldsm4(uint32_t* r, const uint32_t* p) {
    uint32_t a = (uint32_t)__cvta_generic_to_shared(p);
    asm volatile("ldmatrix.sync.aligned.m8n8.x4.shared.b16 {%0,%1,%2,%3}, [%4];"
                 : "=r"(r[0]), "=r"(r[1]), "=r"(r[2]), "=r"(r[3]) : "r"(a));
}
__device__ __forceinline__ void cpasync16(uint32_t dst, const void* src) {
    asm volatile("cp.async.ca.shared.global [%0], [%1], 16;" :: "r"(dst), "l"(src));
}
__device__ __forceinline__ void cp_commit() { asm volatile("cp.async.commit_group;"); }
template <int N> __device__ __forceinline__ void cp_wait() {
    asm volatile("cp.async.wait_group %0;" :: "n"(N));
}

// ---------------- bias precompute (parallelized) --------------------------------
__global__ void bias_kernel(const float* __restrict__ theta_max,
                            const float* __restrict__ a_p, const float* __restrict__ b_p,
                            const float* __restrict__ a_r, const float* __restrict__ b_r,
                            const int*   __restrict__ radius,
                            const int*   __restrict__ azimuth)
{
    const int b = blockIdx.x >> 4;
    const int i = (blockIdx.x & 15) * 256 + threadIdx.x;
    const float tm = theta_max[b];
    const float azc = 2.0f * 3.14159265358979323846f / 64.0f;
    int az = azimuth[i];
    int ai = az < 0 ? az + 15 : az;
    float azf = (float)az * azc;
    float phi = a_p[ai] * cosf(azf) + b_p[ai] * sinf(azf);
    int r = radius[i];
    int ri = r < 0 ? r + 15 : r;
    float rn = (float)r * tm * (1.0f / 64.0f);
    float th = a_r[ri] * cosf(rn) + b_r[ri] * sinf(rn);
    g_bias[b * (NTOK * NTOK) + i] = phi + th;
}

// ---------------- weight-product precompute ------------------------------------
// qkv_w rows: Wq=[0:256), Wk=[256:512), Wv=[512:768)
__global__ void mat_kernel(const float* __restrict__ qkv_w, const float* __restrict__ qkv_b,
                           const float* __restrict__ proj_w, const float* __restrict__ proj_b)
{
    const int b = blockIdx.x, c = threadIdx.x;
    if (b < 256) {                       // M row e: scale * sum_i Wq[i,c]*Wk[i,e]
        int e = b;
        float s0 = 0.f, s1 = 0.f, s2 = 0.f, s3 = 0.f;
        for (int i = 0; i < 256; i += 4) {
            s0 += qkv_w[(i + 0) * 256 + c] * qkv_w[(256 + i + 0) * 256 + e];
            s1 += qkv_w[(i + 1) * 256 + c] * qkv_w[(256 + i + 1) * 256 + e];
            s2 += qkv_w[(i + 2) * 256 + c] * qkv_w[(256 + i + 2) * 256 + e];
            s3 += qkv_w[(i + 3) * 256 + c] * qkv_w[(256 + i + 3) * 256 + e];
        }
        g_Wc[e * 256 + c] = __uint_as_float(f2tf(((s0 + s1) + (s2 + s3)) * SCALE));
    } else if (b < 512) {                // Wz row j: sum_i Wp[j,i]*Wv[i,c]
        int j = b - 256;
        float s0 = 0.f, s1 = 0.f, s2 = 0.f, s3 = 0.f;
        for (int i = 0; i < 256; i += 4) {
            s0 += proj_w[j * 256 + i + 0] * qkv_w[(512 + i + 0) * 256 + c];
            s1 += proj_w[j * 256 + i + 1] * qkv_w[(512 + i + 1) * 256 + c];
            s2 += proj_w[j * 256 + i + 2] * qkv_w[(512 + i + 2) * 256 + c];
            s3 += proj_w[j * 256 + i + 3] * qkv_w[(512 + i + 3) * 256 + c];
        }
        g_Wc[(256 + j) * 256 + c] = __uint_as_float(f2tf((s0 + s1) + (s2 + s3)));
    } else if (b == 512) {               // wv
        float s = 0.f;
        for (int i = 0; i < 256; i++)
            s += qkv_w[(256 + i) * 256 + c] * qkv_b[i];
        g_wv[c] = s;
    } else {                             // d
        float s = proj_b[c];
        for (int i = 0; i < 256; i++)
            s += proj_w[c * 256 + i] * qkv_b[512 + i];
        g_d[c] = s;
    }
}

// ---------------- Kernel A: [G1|Z] = X @ Wc^T -----------------------------------
// BM=128, BN=256, BK=32, 512 threads, 16 warps (2M x 8N), warp tile 64x32.
#define AS_STRIDE 36
#define ASTG (128 * AS_STRIDE)
#define WSTG (256 * AS_STRIDE)
#define GEMM_SMEM_WORDS (2 * ASTG + 2 * WSTG)

__global__ __launch_bounds__(512)
void gemm_g1z_kernel(const float* __restrict__ A)
{
    extern __shared__ uint32_t smem[];
    uint32_t* As = smem;               // [2][128*36] fp32 x chunks
    uint32_t* Ws = smem + 2 * ASTG;    // [2][256*36] tf32 Wc chunks

    const int tid = threadIdx.x, lane = tid & 31, wid = tid >> 5;
    const int g = lane >> 2, tg = lane & 3;
    const int wm0 = (wid & 1) * 64, wn0 = (wid >> 1) * 32;
    const int m0 = blockIdx.y << 7, n0 = blockIdx.x << 8;

    const int lrA = (lane & 7) + ((lane >> 3) & 1) * 8;
    const int lkA = ((lane >> 4) & 1) * 4;
    const int lrB = (lane & 7) + ((lane >> 4) & 1) * 8;
    const int lkB = ((lane >> 3) & 1) * 4;

    const uint32_t sA = (uint32_t)__cvta_generic_to_shared(As);
    const uint32_t sW = (uint32_t)__cvta_generic_to_shared(Ws);

    // A: 1024 chunks (2/thread), W: 2048 chunks (4/thread)
    uint32_t dA[2]; size_t gA[2];
#pragma unroll
    for (int i = 0; i < 2; i++) {
        int lin = tid + (i << 9); int r = lin >> 3, c = (lin & 7) << 2;
        dA[i] = (uint32_t)(r * AS_STRIDE + c) * 4;
        gA[i] = (size_t)(m0 + r) * 256 + c;
    }
    uint32_t dW[4]; size_t gW[4];
#pragma unroll
    for (int i = 0; i < 4; i++) {
        int lin = tid + (i << 9); int r = lin >> 3, c = (lin & 7) << 2;
        dW[i] = (uint32_t)(r * AS_STRIDE + c) * 4;
        gW[i] = (size_t)(n0 + r) * 256 + c;
    }

    float acc[4][4][4] = {};

#define ISSUE(s, k0)                                                    \
    do {                                                                \
        const int _k0 = (k0);                                           \
        uint32_t obA = (uint32_t)(s) * (ASTG * 4);                      \
        uint32_t obW = (uint32_t)(s) * (WSTG * 4);                      \
        _Pragma("unroll")                                               \
        for (int _ci = 0; _ci < 2; _ci++)                               \
            cpasync16(sA + obA + dA[_ci], A + gA[_ci] + _k0);           \
        _Pragma("unroll")                                               \
        for (int _ci = 0; _ci < 4; _ci++)                               \
            cpasync16(sW + obW + dW[_ci], g_Wc + gW[_ci] + _k0);        \
        cp_commit();                                                    \
    } while (0)

    ISSUE(0, 0);
    ISSUE(1, 32);

#pragma unroll
    for (int it = 0; it < 8; it++) {
        const int s = it & 1;
        if (it == 7) cp_wait<0>(); else cp_wait<1>();
        __syncthreads();

        const uint32_t* Ab = As + s * ASTG;
        const uint32_t* Wb = Ws + s * WSTG;
#pragma unroll
        for (int ks = 0; ks < 32; ks += 8) {
            uint32_t a[4][4], b[2][4];
#pragma unroll
            for (int mt = 0; mt < 4; mt++)
                ldsm4(a[mt], &Ab[(wm0 + mt * 16 + lrA) * AS_STRIDE + ks + lkA]);
#pragma unroll
            for (int p = 0; p < 2; p++)
                ldsm4(b[p], &Wb[(wn0 + p * 16 + lrB) * AS_STRIDE + ks + lkB]);
#pragma unroll
            for (int mt = 0; mt < 4; mt++)
#pragma unroll
                for (int j = 0; j < 4; j++) a[mt][j] = u2tf(a[mt][j]);
#pragma unroll
            for (int mt = 0; mt < 4; mt++)
#pragma unroll
                for (int nt = 0; nt < 4; nt++) {
                    int p = nt >> 1, hi = (nt & 1) * 2;
                    mma8(acc[mt][nt], a[mt][0], a[mt][1], a[mt][2], a[mt][3], b[p][hi], b[p][hi + 1]);
                }
        }
        __syncthreads();
        if (it + 2 < 8) ISSUE(s, (it + 2) * 32);
    }
#undef ISSUE

    float* buf = (n0 == 0) ? g_G1 : g_Z;
#pragma unroll
    for (int mt = 0; mt < 4; mt++)
#pragma unroll
        for (int nt = 0; nt < 4; nt++) {
            int coln = wn0 + nt * 8 + 2 * tg;        // 0..255
            int r = m0 + wm0 + mt * 16 + g;
            uint2 v0 = { f2tf(acc[mt][nt][0]), f2tf(acc[mt][nt][1]) };
            uint2 v1 = { f2tf(acc[mt][nt][2]), f2tf(acc[mt][nt][3]) };
            *(uint2*)(buf + (size_t)r * 256 + coln)       = v0;
            *(uint2*)(buf + (size_t)(r + 8) * 256 + coln) = v1;
        }
}

// ---------------- Kernel B: per-window attention (a2 fused) ---------------------
#define SS_STRIDE 68
#define VS_STRIDE 264
#define QS_STRIDE 36
#define OFF_VS  0
#define OFF_SS  (64 * VS_STRIDE)
#define OFF_QS  (OFF_SS + 64 * SS_STRIDE)
#define OFF_KS  (OFF_QS + 64 * QS_STRIDE)
#define OFF_WV  (OFF_KS + 64 * QS_STRIDE)
#define OFF_A2S (OFF_WV + 256)
#define ATTN_SMEM_WORDS (OFF_A2S + 64)

__global__ __launch_bounds__(256, 2)
void attn_kernel(const float* __restrict__ x, float* __restrict__ out)
{
    extern __shared__ uint32_t sm[];
    uint32_t* Vs  = sm + OFF_VS;     // Z tile (tf32)
    uint32_t* Ss  = sm + OFF_SS;     // S fp32 then P tf32
    uint32_t* Qs  = sm + OFF_QS;     // G1 chunk (tf32)
    uint32_t* Ks  = sm + OFF_KS;     // X chunk (tf32)
    float*    wvs = (float*)(sm + OFF_WV);
    float*    a2s = (float*)(sm + OFF_A2S);

    const int tid = threadIdx.x, lane = tid & 31, wid = tid >> 5;
    const int g = lane >> 2, tg = lane & 3;
    const int w = blockIdx.x;
    const size_t base = (size_t)w * NTOK * CDIM;

    const int lrA = (lane & 7) + ((lane >> 3) & 1) * 8;
    const int lkA = ((lane >> 4) & 1) * 4;
    const int lrB = (lane & 7) + ((lane >> 4) & 1) * 8;
    const int lkB = ((lane >> 3) & 1) * 4;

    // wv -> smem (read once)
    wvs[tid] = g_wv[tid];

    // Z -> smem (tf32 pass-through)
#pragma unroll
    for (int i = 0; i < 16; i++) {
        int lin = tid + (i << 8); int r = lin >> 6, c = (lin & 63) << 2;
        uint4 v = *(const uint4*)((const uint32_t*)g_Z + base + r * 256 + c);
        *(uint4*)&Vs[r * VS_STRIDE + c] = v;
    }

    // ---- phase 1: S = G1 @ X^T, warps 4M x 2N; a2 accumulated on the side ----
    const int wm0 = (wid & 3) * 16, wn0 = (wid >> 2) * 32;
    const int a2r = tid >> 2, a2p = tid & 3;
    float a2acc = 0.f;
    float acc1[4][4] = {};
    uint4 rq[2]; float4 rk[2];
#pragma unroll
    for (int i = 0; i < 2; i++) {
        int lin = tid + (i << 8); int r = lin >> 3, c = (lin & 7) << 2;
        rq[i] = *(const uint4*)((const uint32_t*)g_G1 + base + r * 256 + c);
        rk[i] = *(const float4*)(x + base + r * 256 + c);
    }
    for (int k0 = 0; k0 < 256; k0 += 32) {
        __syncthreads();
#pragma unroll
        for (int i = 0; i < 2; i++) {
            int lin = tid + (i << 8); int r = lin >> 3, c = (lin & 7) << 2;
            uint4 uk; uk.x = f2tf(rk[i].x); uk.y = f2tf(rk[i].y);
            uk.z = f2tf(rk[i].z); uk.w = f2tf(rk[i].w);
            *(uint4*)&Qs[r * QS_STRIDE + c] = rq[i];
            *(uint4*)&Ks[r * QS_STRIDE + c] = uk;
        }
        __syncthreads();
        if (k0 < 224) {
#pragma unroll
            for (int i = 0; i < 2; i++) {
                int lin = tid + (i << 8); int r = lin >> 3, c = (lin & 7) << 2;
                rq[i] = *(const uint4*)((const uint32_t*)g_G1 + base + r * 256 + k0 + 32 + c);
                rk[i] = *(const float4*)(x + base + r * 256 + k0 + 32 + c);
            }
        }
        // a2 partial from staged x chunk
#pragma unroll
        for (int j = 0; j < 8; j++) {
            int cl = a2p * 8 + j;
            a2acc += __uint_as_float(Ks[a2r * QS_STRIDE + cl]) * wvs[k0 + cl];
        }
#pragma unroll
        for (int ks = 0; ks < 32; ks += 8) {
            uint32_t a[4], b[2][4];
            ldsm4(a, &Qs[(wm0 + lrA) * QS_STRIDE + ks + lkA]);
#pragma unroll
            for (int p = 0; p < 2; p++)
                ldsm4(b[p], &Ks[(wn0 + p * 16 + lrB) * QS_STRIDE + ks + lkB]);
#pragma unroll
            for (int nt = 0; nt < 4; nt++) {
                int p = nt >> 1, hi = (nt & 1) * 2;
                mma8(acc1[nt], a[0], a[1], a[2], a[3], b[p][hi], b[p][hi + 1]);
            }
        }
    }

    a2acc += __shfl_xor_sync(0xffffffffu, a2acc, 1);
    a2acc += __shfl_xor_sync(0xffffffffu, a2acc, 2);
    if (a2p == 0) a2s[a2r] = a2acc * SCALE;
    __syncthreads();

    // bias + a2 add, stash S (fp32)
    {
        const float* bb = g_bias + (w >> 6) * (NTOK * NTOK);
        float* Sf = (float*)Ss;
#pragma unroll
        for (int nt = 0; nt < 4; nt++) {
            int col = wn0 + nt * 8 + 2 * tg;
            int r0 = wm0 + g;
            float a0 = a2s[col], a1 = a2s[col + 1];
            Sf[r0 * SS_STRIDE + col]           = acc1[nt][0] + bb[r0 * 64 + col]       + a0;
            Sf[r0 * SS_STRIDE + col + 1]       = acc1[nt][1] + bb[r0 * 64 + col + 1]   + a1;
            Sf[(r0 + 8) * SS_STRIDE + col]     = acc1[nt][2] + bb[(r0 + 8) * 64 + col] + a0;
            Sf[(r0 + 8) * SS_STRIDE + col + 1] = acc1[nt][3] + bb[(r0 + 8) * 64 + col + 1] + a1;
        }
    }
    __syncthreads();

    // ---- softmax over keys; P as tf32 ----
    {
        float* Sf = (float*)Ss;
        int r = tid >> 2, p = tid & 3;
        float v[16];
        float mx = -1e30f;
#pragma unroll
        for (int i = 0; i < 16; i++) { v[i] = Sf[r * SS_STRIDE + p + 4 * i]; mx = fmaxf(mx, v[i]); }
        mx = fmaxf(mx, __shfl_xor_sync(0xffffffffu, mx, 1));
        mx = fmaxf(mx, __shfl_xor_sync(0xffffffffu, mx, 2));
        float s = 0.f;
#pragma unroll
        for (int i = 0; i < 16; i++) { v[i] = __expf(v[i] - mx); s += v[i]; }
        s += __shfl_xor_sync(0xffffffffu, s, 1);
        s += __shfl_xor_sync(0xffffffffu, s, 2);
        float inv = 1.0f / s;
#pragma unroll
        for (int i = 0; i < 16; i++) Ss[r * SS_STRIDE + p + 4 * i] = f2tf(v[i] * inv);
    }
    __syncthreads();

    // ---- phase 2: out = P @ Z + d ----
    {
        const int wn = wid * 32;
        float acc2[4][4][4] = {};
#pragma unroll
        for (int ks = 0; ks < 64; ks += 8) {
            uint32_t a[4][4];
#pragma unroll
            for (int mt = 0; mt < 4; mt++)
                ldsm4(a[mt], &Ss[(mt * 16 + lrA) * SS_STRIDE + ks + lkA]);
#pragma unroll
            for (int nt = 0; nt < 4; nt++) {
                uint32_t b0 = Vs[(ks + tg) * VS_STRIDE + wn + nt * 8 + g];
                uint32_t b1 = Vs[(ks + tg + 4) * VS_STRIDE + wn + nt * 8 + g];
#pragma unroll
                for (int mt = 0; mt < 4; mt++)
                    mma8(acc2[mt][nt], a[mt][0], a[mt][1], a[mt][2], a[mt][3], b0, b1);
            }
        }
#pragma unroll
        for (int mt = 0; mt < 4; mt++)
#pragma unroll
            for (int nt = 0; nt < 4; nt++) {
                int col = wn + nt * 8 + 2 * tg, r0 = mt * 16 + g;
                float d0 = g_d[col], d1 = g_d[col + 1];
                float2 v0 = { acc2[mt][nt][0] + d0, acc2[mt][nt][1] + d1 };
                float2 v1 = { acc2[mt][nt][2] + d0, acc2[mt][nt][3] + d1 };
                *(float2*)(out + base + r0 * 256 + col)       = v0;
                *(float2*)(out + base + (r0 + 8) * 256 + col) = v1;
            }
    }
}

// ---------------- launch --------------------------------------------------------
extern "C" void kernel_launch(void* const* d_in, const int* in_sizes, int n_in,
                              void* d_out, int out_size)
{
    const float* x         = (const float*)d_in[0];
    const float* theta_max = (const float*)d_in[1];
    const float* qkv_w     = (const float*)d_in[2];
    const float* qkv_b     = (const float*)d_in[3];
    const float* proj_w    = (const float*)d_in[4];
    const float* proj_b    = (const float*)d_in[5];
    const float* a_p       = (const float*)d_in[6];
    const float* b_p       = (const float*)d_in[7];
    const float* a_r       = (const float*)d_in[8];
    const float* b_r       = (const float*)d_in[9];
    const int*   radius    = (const int*)d_in[10];
    const int*   azimuth   = (const int*)d_in[11];
    float*       out       = (float*)d_out;

    bias_kernel<<<NBATCH * 16, 256>>>(theta_max, a_p, b_p, a_r, b_r, radius, azimuth);
    mat_kernel<<<514, 256>>>(qkv_w, qkv_b, proj_w, proj_b);

    const int gemm_smem = GEMM_SMEM_WORDS * (int)sizeof(uint32_t);
    cudaFuncSetAttribute(gemm_g1z_kernel, cudaFuncAttributeMaxDynamicSharedMemorySize, gemm_smem);
    gemm_g1z_kernel<<<dim3(2, MROWS / 128), 512, gemm_smem>>>(x);

    const int attn_smem = ATTN_SMEM_WORDS * (int)sizeof(uint32_t);
    cudaFuncSetAttribute(attn_kernel, cudaFuncAttributeMaxDynamicSharedMemorySize, attn_smem);
    attn_kernel<<<BWIN, 256, attn_smem>>>(x, out);
}

// round 15
// speedup vs baseline: 1.1244x; 1.1244x over previous
#include <cuda_runtime.h>
#include <math.h>
#include <stdint.h>

#define BWIN   2048
#define NTOK   64
#define CDIM   256
#define MROWS  (BWIN * NTOK)
#define NBATCH 32
#define SCALE  0.0625f

// ---------------- scratch ----------------------------------------------------
__device__ float g_bias[NBATCH * NTOK * NTOK];
__device__ float g_Wc[512 * CDIM];    // tf32 bits: rows 0-255 = M, 256-511 = Wz
__device__ float g_wv[CDIM];
__device__ float g_d [CDIM];
__device__ float g_G1[MROWS * CDIM];  // tf32
__device__ float g_Z [MROWS * CDIM];  // tf32

// ---------------- helpers -----------------------------------------------------
__device__ __forceinline__ uint32_t f2tf(float f) {
    uint32_t u; asm("cvt.rna.tf32.f32 %0, %1;" : "=r"(u) : "f"(f)); return u;
}
__device__ __forceinline__ uint32_t u2tf(uint32_t x) {
    uint32_t u; asm("cvt.rna.tf32.f32 %0, %1;" : "=r"(u) : "f"(__uint_as_float(x))); return u;
}
__device__ __forceinline__ void mma8(float* c, uint32_t a0, uint32_t a1, uint32_t a2, uint32_t a3,
                                     uint32_t b0, uint32_t b1) {
    asm volatile(
        "mma.sync.aligned.m16n8k8.row.col.f32.tf32.tf32.f32 "
        "{%0,%1,%2,%3},{%4,%5,%6,%7},{%8,%9},{%0,%1,%2,%3};"
        : "+f"(c[0]), "+f"(c[1]), "+f"(c[2]), "+f"(c[3])
        : "r"(a0), "r"(a1), "r"(a2), "r"(a3), "r"(b0), "r"(b1));
}
__device__ __forceinline__ void ldsm4(uint32_t* r, const uint32_t* p) {
    uint32_t a = (uint32_t)__cvta_generic_to_shared(p);
    asm volatile("ldmatrix.sync.aligned.m8n8.x4.shared.b16 {%0,%1,%2,%3}, [%4];"
                 : "=r"(r[0]), "=r"(r[1]), "=r"(r[2]), "=r"(r[3]) : "r"(a));
}
__device__ __forceinline__ void cpasync16(uint32_t dst, const void* src) {
    asm volatile("cp.async.ca.shared.global [%0], [%1], 16;" :: "r"(dst), "l"(src));
}
__device__ __forceinline__ void cp_commit() { asm volatile("cp.async.commit_group;"); }
template <int N> __device__ __forceinline__ void cp_wait() {
    asm volatile("cp.async.wait_group %0;" :: "n"(N));
}

// ---------------- bias precompute ---------------------------------------------
__global__ void bias_kernel(const float* __restrict__ theta_max,
                            const float* __restrict__ a_p, const float* __restrict__ b_p,
                            const float* __restrict__ a_r, const float* __restrict__ b_r,
                            const int*   __restrict__ radius,
                            const int*   __restrict__ azimuth)
{
    const int b = blockIdx.x >> 4;
    const int i = (blockIdx.x & 15) * 256 + threadIdx.x;
    const float tm = theta_max[b];
    const float azc = 2.0f * 3.14159265358979323846f / 64.0f;
    int az = azimuth[i];
    int ai = az < 0 ? az + 15 : az;
    float azf = (float)az * azc;
    float phi = a_p[ai] * cosf(azf) + b_p[ai] * sinf(azf);
    int r = radius[i];
    int ri = r < 0 ? r + 15 : r;
    float rn = (float)r * tm * (1.0f / 64.0f);
    float th = a_r[ri] * cosf(rn) + b_r[ri] * sinf(rn);
    g_bias[b * (NTOK * NTOK) + i] = phi + th;
}

// ---------------- weight-product precompute ------------------------------------
__global__ void mat_kernel(const float* __restrict__ qkv_w, const float* __restrict__ qkv_b,
                           const float* __restrict__ proj_w, const float* __restrict__ proj_b)
{
    const int b = blockIdx.x, c = threadIdx.x;
    if (b < 256) {
        int e = b;
        float s0 = 0.f, s1 = 0.f, s2 = 0.f, s3 = 0.f;
        for (int i = 0; i < 256; i += 4) {
            s0 += qkv_w[(i + 0) * 256 + c] * qkv_w[(256 + i + 0) * 256 + e];
            s1 += qkv_w[(i + 1) * 256 + c] * qkv_w[(256 + i + 1) * 256 + e];
            s2 += qkv_w[(i + 2) * 256 + c] * qkv_w[(256 + i + 2) * 256 + e];
            s3 += qkv_w[(i + 3) * 256 + c] * qkv_w[(256 + i + 3) * 256 + e];
        }
        g_Wc[e * 256 + c] = __uint_as_float(f2tf(((s0 + s1) + (s2 + s3)) * SCALE));
    } else if (b < 512) {
        int j = b - 256;
        float s0 = 0.f, s1 = 0.f, s2 = 0.f, s3 = 0.f;
        for (int i = 0; i < 256; i += 4) {
            s0 += proj_w[j * 256 + i + 0] * qkv_w[(512 + i + 0) * 256 + c];
            s1 += proj_w[j * 256 + i + 1] * qkv_w[(512 + i + 1) * 256 + c];
            s2 += proj_w[j * 256 + i + 2] * qkv_w[(512 + i + 2) * 256 + c];
            s3 += proj_w[j * 256 + i + 3] * qkv_w[(512 + i + 3) * 256 + c];
        }
        g_Wc[(256 + j) * 256 + c] = __uint_as_float(f2tf((s0 + s1) + (s2 + s3)));
    } else if (b == 512) {
        float s = 0.f;
        for (int i = 0; i < 256; i++)
            s += qkv_w[(256 + i) * 256 + c] * qkv_b[i];
        g_wv[c] = s;
    } else {
        float s = proj_b[c];
        for (int i = 0; i < 256; i++)
            s += proj_w[c * 256 + i] * qkv_b[512 + i];
        g_d[c] = s;
    }
}

// ---------------- Kernel A: [G1|Z] = X @ Wc^T  (R13 proven shape) ---------------
// BM=128, BN=256, BK=32, 256 threads, 8 warps (2M x 4N), warp tile 64x64.
#define AS_STRIDE 36
#define ASTG (128 * AS_STRIDE)
#define WSTG (256 * AS_STRIDE)
#define GEMM_SMEM_WORDS (2 * ASTG + 2 * WSTG)

__global__ __launch_bounds__(256)
void gemm_g1z_kernel(const float* __restrict__ A)
{
    extern __shared__ uint32_t smem[];
    uint32_t* As = smem;
    uint32_t* Ws = smem + 2 * ASTG;

    const int tid = threadIdx.x, lane = tid & 31, wid = tid >> 5;
    const int g = lane >> 2, tg = lane & 3;
    const int wm0 = (wid & 1) * 64, wn0 = (wid >> 1) * 64;
    const int m0 = blockIdx.y << 7, n0 = blockIdx.x << 8;

    const int lrA = (lane & 7) + ((lane >> 3) & 1) * 8;
    const int lkA = ((lane >> 4) & 1) * 4;
    const int lrB = (lane & 7) + ((lane >> 4) & 1) * 8;
    const int lkB = ((lane >> 3) & 1) * 4;

    const uint32_t sA = (uint32_t)__cvta_generic_to_shared(As);
    const uint32_t sW = (uint32_t)__cvta_generic_to_shared(Ws);

    uint32_t dA[4]; size_t gA[4];
#pragma unroll
    for (int i = 0; i < 4; i++) {
        int lin = tid + (i << 8); int r = lin >> 3, c = (lin & 7) << 2;
        dA[i] = (uint32_t)(r * AS_STRIDE + c) * 4;
        gA[i] = (size_t)(m0 + r) * 256 + c;
    }
    uint32_t dW[8]; size_t gW[8];
#pragma unroll
    for (int i = 0; i < 8; i++) {
        int lin = tid + (i << 8); int r = lin >> 3, c = (lin & 7) << 2;
        dW[i] = (uint32_t)(r * AS_STRIDE + c) * 4;
        gW[i] = (size_t)(n0 + r) * 256 + c;
    }

    float acc[4][8][4] = {};

#define ISSUE(s, k0)                                                    \
    do {                                                                \
        const int _k0 = (k0);                                           \
        uint32_t obA = (uint32_t)(s) * (ASTG * 4);                      \
        uint32_t obW = (uint32_t)(s) * (WSTG * 4);                      \
        _Pragma("unroll")                                               \
        for (int _ci = 0; _ci < 4; _ci++)                               \
            cpasync16(sA + obA + dA[_ci], A + gA[_ci] + _k0);           \
        _Pragma("unroll")                                               \
        for (int _ci = 0; _ci < 8; _ci++)                               \
            cpasync16(sW + obW + dW[_ci], g_Wc + gW[_ci] + _k0);        \
        cp_commit();                                                    \
    } while (0)

    ISSUE(0, 0);
    ISSUE(1, 32);

#pragma unroll
    for (int it = 0; it < 8; it++) {
        const int s = it & 1;
        if (it == 7) cp_wait<0>(); else cp_wait<1>();
        __syncthreads();

        const uint32_t* Ab = As + s * ASTG;
        const uint32_t* Wb = Ws + s * WSTG;
#pragma unroll
        for (int ks = 0; ks < 32; ks += 8) {
            uint32_t a[4][4], b[4][4];
#pragma unroll
            for (int mt = 0; mt < 4; mt++)
                ldsm4(a[mt], &Ab[(wm0 + mt * 16 + lrA) * AS_STRIDE + ks + lkA]);
#pragma unroll
            for (int p = 0; p < 4; p++)
                ldsm4(b[p], &Wb[(wn0 + p * 16 + lrB) * AS_STRIDE + ks + lkB]);
#pragma unroll
            for (int mt = 0; mt < 4; mt++)
#pragma unroll
                for (int j = 0; j < 4; j++) a[mt][j] = u2tf(a[mt][j]);
#pragma unroll
            for (int mt = 0; mt < 4; mt++)
#pragma unroll
                for (int nt = 0; nt < 8; nt++) {
                    int p = nt >> 1, hi = (nt & 1) * 2;
                    mma8(acc[mt][nt], a[mt][0], a[mt][1], a[mt][2], a[mt][3], b[p][hi], b[p][hi + 1]);
                }
        }
        __syncthreads();
        if (it + 2 < 8) ISSUE(s, (it + 2) * 32);
    }
#undef ISSUE

    float* buf = (n0 == 0) ? g_G1 : g_Z;
#pragma unroll
    for (int mt = 0; mt < 4; mt++)
#pragma unroll
        for (int nt = 0; nt < 8; nt++) {
            int coln = wn0 + nt * 8 + 2 * tg;
            int r = m0 + wm0 + mt * 16 + g;
            uint2 v0 = { f2tf(acc[mt][nt][0]), f2tf(acc[mt][nt][1]) };
            uint2 v1 = { f2tf(acc[mt][nt][2]), f2tf(acc[mt][nt][3]) };
            *(uint2*)(buf + (size_t)r * 256 + coln)       = v0;
            *(uint2*)(buf + (size_t)(r + 8) * 256 + coln) = v1;
        }
}

// ---------------- Kernel B: per-window attention --------------------------------
// Phase 1: S = G1 @ X^T via 2-stage cp.async staging (+ fused a2).
// Phase 2: out = P @ Z + d with Z B-fragments read directly from global.
#define SS_STRIDE 68
#define QS_STRIDE 36
#define QSTG (64 * QS_STRIDE)                 // 2304 words per stage
#define OFF_SS  0
#define OFF_QST (64 * SS_STRIDE)              // 4352
#define OFF_KST (OFF_QST + 2 * QSTG)          // 8960
#define OFF_WV  (OFF_KST + 2 * QSTG)          // 13568
#define OFF_A2S (OFF_WV + 256)                // 13824
#define ATTN_SMEM_WORDS (OFF_A2S + 64)        // 13888 words = 55552 B

__global__ __launch_bounds__(256, 2)
void attn_kernel(const float* __restrict__ x, float* __restrict__ out)
{
    extern __shared__ uint32_t sm[];
    uint32_t* Ss  = sm + OFF_SS;
    uint32_t* Qst = sm + OFF_QST;
    uint32_t* Kst = sm + OFF_KST;
    float*    wvs = (float*)(sm + OFF_WV);
    float*    a2s = (float*)(sm + OFF_A2S);

    const int tid = threadIdx.x, lane = tid & 31, wid = tid >> 5;
    const int g = lane >> 2, tg = lane & 3;
    const int w = blockIdx.x;
    const size_t base = (size_t)w * NTOK * CDIM;

    const int lrA = (lane & 7) + ((lane >> 3) & 1) * 8;
    const int lkA = ((lane >> 4) & 1) * 4;
    const int lrB = (lane & 7) + ((lane >> 4) & 1) * 8;
    const int lkB = ((lane >> 3) & 1) * 4;

    wvs[tid] = g_wv[tid];

    const uint32_t sQ = (uint32_t)__cvta_generic_to_shared(Qst);
    const uint32_t sK = (uint32_t)__cvta_generic_to_shared(Kst);

    // staging map: 64 rows x 32 k = 512 x 16B chunks per array, 2/thread
    uint32_t dQ[2]; size_t gOf[2];
#pragma unroll
    for (int i = 0; i < 2; i++) {
        int lin = tid + (i << 8); int r = lin >> 3, c = (lin & 7) << 2;
        dQ[i]  = (uint32_t)(r * QS_STRIDE + c) * 4;
        gOf[i] = (size_t)r * 256 + c;
    }

#define ISSUE_QK(s, k0)                                                       \
    do {                                                                      \
        const int _k0 = (k0);                                                 \
        uint32_t _ob = (uint32_t)(s) * (QSTG * 4);                            \
        _Pragma("unroll")                                                     \
        for (int _ci = 0; _ci < 2; _ci++) {                                   \
            cpasync16(sQ + _ob + dQ[_ci], (const float*)g_G1 + base + gOf[_ci] + _k0); \
            cpasync16(sK + _ob + dQ[_ci], x + base + gOf[_ci] + _k0);         \
        }                                                                     \
        cp_commit();                                                          \
    } while (0)

    ISSUE_QK(0, 0);
    ISSUE_QK(1, 32);

    // ---- phase 1: S = G1 @ X^T, warps 4M x 2N; a2 fused ----
    const int wm0 = (wid & 3) * 16, wn0 = (wid >> 2) * 32;
    const int a2r = tid >> 2, a2p = tid & 3;
    float a2acc = 0.f;
    float acc1[4][4] = {};

#pragma unroll
    for (int it = 0; it < 8; it++) {
        const int s = it & 1;
        if (it == 7) cp_wait<0>(); else cp_wait<1>();
        __syncthreads();

        const uint32_t* Qb = Qst + s * QSTG;
        const uint32_t* Kb = Kst + s * QSTG;

        // a2 partial from staged fp32 x chunk
#pragma unroll
        for (int j = 0; j < 8; j++) {
            int cl = a2p * 8 + j;
            a2acc += __uint_as_float(Kb[a2r * QS_STRIDE + cl]) * wvs[it * 32 + cl];
        }

#pragma unroll
        for (int ks = 0; ks < 32; ks += 8) {
            uint32_t a[4], b[2][4];
            ldsm4(a, &Qb[(wm0 + lrA) * QS_STRIDE + ks + lkA]);
#pragma unroll
            for (int p = 0; p < 2; p++)
                ldsm4(b[p], &Kb[(wn0 + p * 16 + lrB) * QS_STRIDE + ks + lkB]);
#pragma unroll
            for (int p = 0; p < 2; p++)
#pragma unroll
                for (int j = 0; j < 4; j++) b[p][j] = u2tf(b[p][j]);
#pragma unroll
            for (int nt = 0; nt < 4; nt++) {
                int p = nt >> 1, hi = (nt & 1) * 2;
                mma8(acc1[nt], a[0], a[1], a[2], a[3], b[p][hi], b[p][hi + 1]);
            }
        }
        __syncthreads();
        if (it + 2 < 8) ISSUE_QK(s, (it + 2) * 32);
    }
#undef ISSUE_QK

    a2acc += __shfl_xor_sync(0xffffffffu, a2acc, 1);
    a2acc += __shfl_xor_sync(0xffffffffu, a2acc, 2);
    if (a2p == 0) a2s[a2r] = a2acc * SCALE;
    __syncthreads();

    // bias + a2 add, stash S (fp32)
    {
        const float* bb = g_bias + (w >> 6) * (NTOK * NTOK);
        float* Sf = (float*)Ss;
#pragma unroll
        for (int nt = 0; nt < 4; nt++) {
            int col = wn0 + nt * 8 + 2 * tg;
            int r0 = wm0 + g;
            float a0 = a2s[col], a1 = a2s[col + 1];
            Sf[r0 * SS_STRIDE + col]           = acc1[nt][0] + bb[r0 * 64 + col]       + a0;
            Sf[r0 * SS_STRIDE + col + 1]       = acc1[nt][1] + bb[r0 * 64 + col + 1]   + a1;
            Sf[(r0 + 8) * SS_STRIDE + col]     = acc1[nt][2] + bb[(r0 + 8) * 64 + col] + a0;
            Sf[(r0 + 8) * SS_STRIDE + col + 1] = acc1[nt][3] + bb[(r0 + 8) * 64 + col + 1] + a1;
        }
    }
    __syncthreads();

    // ---- softmax over keys; P as tf32 ----
    {
        float* Sf = (float*)Ss;
        int r = tid >> 2, p = tid & 3;
        float v[16];
        float mx = -1e30f;
#pragma unroll
        for (int i = 0; i < 16; i++) { v[i] = Sf[r * SS_STRIDE + p + 4 * i]; mx = fmaxf(mx, v[i]); }
        mx = fmaxf(mx, __shfl_xor_sync(0xffffffffu, mx, 1));
        mx = fmaxf(mx, __shfl_xor_sync(0xffffffffu, mx, 2));
        float s = 0.f;
#pragma unroll
        for (int i = 0; i < 16; i++) { v[i] = __expf(v[i] - mx); s += v[i]; }
        s += __shfl_xor_sync(0xffffffffu, s, 1);
        s += __shfl_xor_sync(0xffffffffu, s, 2);
        float inv = 1.0f / s;
#pragma unroll
        for (int i = 0; i < 16; i++) Ss[r * SS_STRIDE + p + 4 * i] = f2tf(v[i] * inv);
    }
    __syncthreads();

    // ---- phase 2: out = P @ Z + d, Z fragments direct from global ----
    {
        const int wn = wid * 32;
        const uint32_t* Zp = (const uint32_t*)g_Z + base;
        float acc2[4][4][4] = {};
#pragma unroll
        for (int ks = 0; ks < 64; ks += 8) {
            uint32_t a[4][4];
#pragma unroll
            for (int mt = 0; mt < 4; mt++)
                ldsm4(a[mt], &Ss[(mt * 16 + lrA) * SS_STRIDE + ks + lkA]);
            uint32_t b0[4], b1[4];
#pragma unroll
            for (int nt = 0; nt < 4; nt++) {
                b0[nt] = Zp[(ks + tg) * 256 + wn + nt * 8 + g];
                b1[nt] = Zp[(ks + tg + 4) * 256 + wn + nt * 8 + g];
            }
#pragma unroll
            for (int nt = 0; nt < 4; nt++)
#pragma unroll
                for (int mt = 0; mt < 4; mt++)
                    mma8(acc2[mt][nt], a[mt][0], a[mt][1], a[mt][2], a[mt][3], b0[nt], b1[nt]);
        }
#pragma unroll
        for (int mt = 0; mt < 4; mt++)
#pragma unroll
            for (int nt = 0; nt < 4; nt++) {
                int col = wn + nt * 8 + 2 * tg, r0 = mt * 16 + g;
                float d0 = g_d[col], d1 = g_d[col + 1];
                float2 v0 = { acc2[mt][nt][0] + d0, acc2[mt][nt][1] + d1 };
                float2 v1 = { acc2[mt][nt][2] + d0, acc2[mt][nt][3] + d1 };
                *(float2*)(out + base + r0 * 256 + col)       = v0;
                *(float2*)(out + base + (r0 + 8) * 256 + col) = v1;
            }
    }
}

// ---------------- launch --------------------------------------------------------
extern "C" void kernel_launch(void* const* d_in, const int* in_sizes, int n_in,
                              void* d_out, int out_size)
{
    const float* x         = (const float*)d_in[0];
    const float* theta_max = (const float*)d_in[1];
    const float* qkv_w     = (const float*)d_in[2];
    const float* qkv_b     = (const float*)d_in[3];
    const float* proj_w    = (const float*)d_in[4];
    const float* proj_b    = (const float*)d_in[5];
    const float* a_p       = (const float*)d_in[6];
    const float* b_p       = (const float*)d_in[7];
    const float* a_r       = (const float*)d_in[8];
    const float* b_r       = (const float*)d_in[9];
    const int*   radius    = (const int*)d_in[10];
    const int*   azimuth   = (const int*)d_in[11];
    float*       out       = (float*)d_out;

    bias_kernel<<<NBATCH * 16, 256>>>(theta_max, a_p, b_p, a_r, b_r, radius, azimuth);
    mat_kernel<<<514, 256>>>(qkv_w, qkv_b, proj_w, proj_b);

    const int gemm_smem = GEMM_SMEM_WORDS * (int)sizeof(uint32_t);
    cudaFuncSetAttribute(gemm_g1z_kernel, cudaFuncAttributeMaxDynamicSharedMemorySize, gemm_smem);
    gemm_g1z_kernel<<<dim3(2, MROWS / 128), 256, gemm_smem>>>(x);

    const int attn_smem = ATTN_SMEM_WORDS * (int)sizeof(uint32_t);
    cudaFuncSetAttribute(attn_kernel, cudaFuncAttributeMaxDynamicSharedMemorySize, attn_smem);
    attn_kernel<<<BWIN, 256, attn_smem>>>(x, out);
}

// round 16
// speedup vs baseline: 1.1570x; 1.0291x over previous
#include <cuda_runtime.h>
#include <math.h>
#include <stdint.h>

#define BWIN   2048
#define NTOK   64
#define CDIM   256
#define MROWS  (BWIN * NTOK)
#define NBATCH 32
#define SCALE  0.0625f

// ---------------- scratch ----------------------------------------------------
__device__ float g_bias[NBATCH * NTOK * NTOK];
__device__ float g_Wc[512 * CDIM];    // tf32 bits: rows 0-255 = M, 256-511 = Wz
__device__ float g_wv[CDIM];
__device__ float g_d [CDIM];
__device__ float g_G1[MROWS * CDIM];  // tf32
__device__ float g_Z [MROWS * CDIM];  // tf32

// ---------------- helpers -----------------------------------------------------
__device__ __forceinline__ uint32_t f2tf(float f) {
    uint32_t u; asm("cvt.rna.tf32.f32 %0, %1;" : "=r"(u) : "f"(f)); return u;
}
__device__ __forceinline__ uint32_t u2tf(uint32_t x) {
    uint32_t u; asm("cvt.rna.tf32.f32 %0, %1;" : "=r"(u) : "f"(__uint_as_float(x))); return u;
}
__device__ __forceinline__ void mma8(float* c, uint32_t a0, uint32_t a1, uint32_t a2, uint32_t a3,
                                     uint32_t b0, uint32_t b1) {
    asm volatile(
        "mma.sync.aligned.m16n8k8.row.col.f32.tf32.tf32.f32 "
        "{%0,%1,%2,%3},{%4,%5,%6,%7},{%8,%9},{%0,%1,%2,%3};"
        : "+f"(c[0]), "+f"(c[1]), "+f"(c[2]), "+f"(c[3])
        : "r"(a0), "r"(a1), "r"(a2), "r"(a3), "r"(b0), "r"(b1));
}
__device__ __forceinline__ void ldsm4(uint32_t* r, const uint32_t* p) {
    uint32_t a = (uint32_t)__cvta_generic_to_shared(p);
    asm volatile("ldmatrix.sync.aligned.m8n8.x4.shared.b16 {%0,%1,%2,%3}, [%4];"
                 : "=r"(r[0]), "=r"(r[1]), "=r"(r[2]), "=r"(r[3]) : "r"(a));
}
__device__ __forceinline__ void cpasync16(uint32_t dst, const void* src) {
    asm volatile("cp.async.ca.shared.global [%0], [%1], 16;" :: "r"(dst), "l"(src));
}
__device__ __forceinline__ void cp_commit() { asm volatile("cp.async.commit_group;"); }
template <int N> __device__ __forceinline__ void cp_wait() {
    asm volatile("cp.async.wait_group %0;" :: "n"(N));
}

// ---------------- bias precompute ---------------------------------------------
__global__ void bias_kernel(const float* __restrict__ theta_max,
                            const float* __restrict__ a_p, const float* __restrict__ b_p,
                            const float* __restrict__ a_r, const float* __restrict__ b_r,
                            const int*   __restrict__ radius,
                            const int*   __restrict__ azimuth)
{
    const int b = blockIdx.x >> 4;
    const int i = (blockIdx.x & 15) * 256 + threadIdx.x;
    const float tm = theta_max[b];
    const float azc = 2.0f * 3.14159265358979323846f / 64.0f;
    int az = azimuth[i];
    int ai = az < 0 ? az + 15 : az;
    float azf = (float)az * azc;
    float phi = a_p[ai] * cosf(azf) + b_p[ai] * sinf(azf);
    int r = radius[i];
    int ri = r < 0 ? r + 15 : r;
    float rn = (float)r * tm * (1.0f / 64.0f);
    float th = a_r[ri] * cosf(rn) + b_r[ri] * sinf(rn);
    g_bias[b * (NTOK * NTOK) + i] = phi + th;
}

// ---------------- weight-product precompute (blocked) ---------------------------
// grid 130: b<64 -> 4 rows of M; b<128 -> 4 rows of Wz; 128 -> wv; 129 -> d.
__global__ __launch_bounds__(256)
void mat_kernel(const float* __restrict__ qkv_w, const float* __restrict__ qkv_b,
                const float* __restrict__ proj_w, const float* __restrict__ proj_b)
{
    __shared__ float pane[4][256];
    const int b = blockIdx.x, c = threadIdx.x;
    if (b < 64) {                        // M rows e0..e0+3
        const int e0 = b * 4;
        // stage Wk[:, e0..e0+3]: pane[j][i]
        for (int t = 0; t < 4; t++) {
            int idx = c + t * 256;       // 1024 elements
            int i = idx >> 2, j = idx & 3;
            pane[j][i] = qkv_w[(256 + i) * 256 + e0 + j];
        }
        __syncthreads();
        float acc[4] = {};
        for (int i = 0; i < 256; i++) {
            float wq = qkv_w[i * 256 + c];
            acc[0] += wq * pane[0][i];
            acc[1] += wq * pane[1][i];
            acc[2] += wq * pane[2][i];
            acc[3] += wq * pane[3][i];
        }
#pragma unroll
        for (int j = 0; j < 4; j++)
            g_Wc[(e0 + j) * 256 + c] = __uint_as_float(f2tf(acc[j] * SCALE));
    } else if (b < 128) {                // Wz rows j0..j0+3
        const int j0 = (b - 64) * 4;
        for (int t = 0; t < 4; t++) {
            int idx = c + t * 256;
            int j = idx >> 8, i = idx & 255;
            pane[j][i] = proj_w[(j0 + j) * 256 + i];
        }
        __syncthreads();
        float acc[4] = {};
        for (int i = 0; i < 256; i++) {
            float wv = qkv_w[(512 + i) * 256 + c];
            acc[0] += pane[0][i] * wv;
            acc[1] += pane[1][i] * wv;
            acc[2] += pane[2][i] * wv;
            acc[3] += pane[3][i] * wv;
        }
#pragma unroll
        for (int j = 0; j < 4; j++)
            g_Wc[(256 + j0 + j) * 256 + c] = __uint_as_float(f2tf(acc[j]));
    } else if (b == 128) {
        float s = 0.f;
        for (int i = 0; i < 256; i++)
            s += qkv_w[(256 + i) * 256 + c] * qkv_b[i];
        g_wv[c] = s;
    } else {
        float s = proj_b[c];
        for (int i = 0; i < 256; i++)
            s += proj_w[c * 256 + i] * qkv_b[512 + i];
        g_d[c] = s;
    }
}

// ---------------- Kernel A: [G1|Z] = X @ Wc^T, 3-stage / single-sync ------------
// BM=128, BN=256, BK=32, 256 threads, 8 warps (2M x 4N), warp tile 64x64.
#define AS_STRIDE 36
#define ASTG (128 * AS_STRIDE)
#define WSTG (256 * AS_STRIDE)
#define GEMM_SMEM_WORDS (3 * (ASTG + WSTG))

__global__ __launch_bounds__(256)
void gemm_g1z_kernel(const float* __restrict__ A)
{
    extern __shared__ uint32_t smem[];
    uint32_t* As = smem;               // [3][128*36]
    uint32_t* Ws = smem + 3 * ASTG;    // [3][256*36]

    const int tid = threadIdx.x, lane = tid & 31, wid = tid >> 5;
    const int g = lane >> 2, tg = lane & 3;
    const int wm0 = (wid & 1) * 64, wn0 = (wid >> 1) * 64;
    const int m0 = blockIdx.y << 7, n0 = blockIdx.x << 8;

    const int lrA = (lane & 7) + ((lane >> 3) & 1) * 8;
    const int lkA = ((lane >> 4) & 1) * 4;
    const int lrB = (lane & 7) + ((lane >> 4) & 1) * 8;
    const int lkB = ((lane >> 3) & 1) * 4;

    const uint32_t sA = (uint32_t)__cvta_generic_to_shared(As);
    const uint32_t sW = (uint32_t)__cvta_generic_to_shared(Ws);

    uint32_t dA[4]; size_t gA[4];
#pragma unroll
    for (int i = 0; i < 4; i++) {
        int lin = tid + (i << 8); int r = lin >> 3, c = (lin & 7) << 2;
        dA[i] = (uint32_t)(r * AS_STRIDE + c) * 4;
        gA[i] = (size_t)(m0 + r) * 256 + c;
    }
    uint32_t dW[8]; size_t gW[8];
#pragma unroll
    for (int i = 0; i < 8; i++) {
        int lin = tid + (i << 8); int r = lin >> 3, c = (lin & 7) << 2;
        dW[i] = (uint32_t)(r * AS_STRIDE + c) * 4;
        gW[i] = (size_t)(n0 + r) * 256 + c;
    }

    float acc[4][8][4] = {};

#define ISSUE(s, k0)                                                    \
    do {                                                                \
        const int _k0 = (k0);                                           \
        uint32_t obA = (uint32_t)(s) * (ASTG * 4);                      \
        uint32_t obW = (uint32_t)(s) * (WSTG * 4);                      \
        _Pragma("unroll")                                               \
        for (int _ci = 0; _ci < 4; _ci++)                               \
            cpasync16(sA + obA + dA[_ci], A + gA[_ci] + _k0);           \
        _Pragma("unroll")                                               \
        for (int _ci = 0; _ci < 8; _ci++)                               \
            cpasync16(sW + obW + dW[_ci], g_Wc + gW[_ci] + _k0);        \
        cp_commit();                                                    \
    } while (0)

    ISSUE(0, 0);
    ISSUE(1, 32);

#pragma unroll
    for (int it = 0; it < 8; it++) {
        const int s = it % 3;
        if (it == 7) cp_wait<0>(); else cp_wait<1>();
        __syncthreads();

        const uint32_t* Ab = As + s * ASTG;
        const uint32_t* Wb = Ws + s * WSTG;
#pragma unroll
        for (int ks = 0; ks < 32; ks += 8) {
            uint32_t a[4][4], b[4][4];
#pragma unroll
            for (int mt = 0; mt < 4; mt++)
                ldsm4(a[mt], &Ab[(wm0 + mt * 16 + lrA) * AS_STRIDE + ks + lkA]);
#pragma unroll
            for (int p = 0; p < 4; p++)
                ldsm4(b[p], &Wb[(wn0 + p * 16 + lrB) * AS_STRIDE + ks + lkB]);
#pragma unroll
            for (int mt = 0; mt < 4; mt++)
#pragma unroll
                for (int j = 0; j < 4; j++) a[mt][j] = u2tf(a[mt][j]);
#pragma unroll
            for (int mt = 0; mt < 4; mt++)
#pragma unroll
                for (int nt = 0; nt < 8; nt++) {
                    int p = nt >> 1, hi = (nt & 1) * 2;
                    mma8(acc[mt][nt], a[mt][0], a[mt][1], a[mt][2], a[mt][3], b[p][hi], b[p][hi + 1]);
                }
        }
        // stage (it+2)%3 == (it-1)%3 was freed by the sync above (all warps done with it-1)
        if (it + 2 < 8) ISSUE((it + 2) % 3, (it + 2) * 32);
    }
#undef ISSUE

    float* buf = (n0 == 0) ? g_G1 : g_Z;
#pragma unroll
    for (int mt = 0; mt < 4; mt++)
#pragma unroll
        for (int nt = 0; nt < 8; nt++) {
            int coln = wn0 + nt * 8 + 2 * tg;
            int r = m0 + wm0 + mt * 16 + g;
            uint2 v0 = { f2tf(acc[mt][nt][0]), f2tf(acc[mt][nt][1]) };
            uint2 v1 = { f2tf(acc[mt][nt][2]), f2tf(acc[mt][nt][3]) };
            *(uint2*)(buf + (size_t)r * 256 + coln)       = v0;
            *(uint2*)(buf + (size_t)(r + 8) * 256 + coln) = v1;
        }
}

// ---------------- Kernel B: per-window attention, 3-stage phase-1 ---------------
#define SS_STRIDE 68
#define QS_STRIDE 36
#define QSTG (64 * QS_STRIDE)                 // 2304 words per stage
#define OFF_SS  0
#define OFF_QST (64 * SS_STRIDE)              // 4352
#define OFF_KST (OFF_QST + 3 * QSTG)          // 11264
#define OFF_WV  (OFF_KST + 3 * QSTG)          // 18176
#define OFF_A2S (OFF_WV + 256)                // 18432
#define ATTN_SMEM_WORDS (OFF_A2S + 64)        // 18496 words = 73984 B

__global__ __launch_bounds__(256, 2)
void attn_kernel(const float* __restrict__ x, float* __restrict__ out)
{
    extern __shared__ uint32_t sm[];
    uint32_t* Ss  = sm + OFF_SS;
    uint32_t* Qst = sm + OFF_QST;
    uint32_t* Kst = sm + OFF_KST;
    float*    wvs = (float*)(sm + OFF_WV);
    float*    a2s = (float*)(sm + OFF_A2S);

    const int tid = threadIdx.x, lane = tid & 31, wid = tid >> 5;
    const int g = lane >> 2, tg = lane & 3;
    const int w = blockIdx.x;
    const size_t base = (size_t)w * NTOK * CDIM;

    const int lrA = (lane & 7) + ((lane >> 3) & 1) * 8;
    const int lkA = ((lane >> 4) & 1) * 4;
    const int lrB = (lane & 7) + ((lane >> 4) & 1) * 8;
    const int lkB = ((lane >> 3) & 1) * 4;

    wvs[tid] = g_wv[tid];

    const uint32_t sQ = (uint32_t)__cvta_generic_to_shared(Qst);
    const uint32_t sK = (uint32_t)__cvta_generic_to_shared(Kst);

    uint32_t dQ[2]; size_t gOf[2];
#pragma unroll
    for (int i = 0; i < 2; i++) {
        int lin = tid + (i << 8); int r = lin >> 3, c = (lin & 7) << 2;
        dQ[i]  = (uint32_t)(r * QS_STRIDE + c) * 4;
        gOf[i] = (size_t)r * 256 + c;
    }

#define ISSUE_QK(s, k0)                                                       \
    do {                                                                      \
        const int _k0 = (k0);                                                 \
        uint32_t _ob = (uint32_t)(s) * (QSTG * 4);                            \
        _Pragma("unroll")                                                     \
        for (int _ci = 0; _ci < 2; _ci++) {                                   \
            cpasync16(sQ + _ob + dQ[_ci], (const float*)g_G1 + base + gOf[_ci] + _k0); \
            cpasync16(sK + _ob + dQ[_ci], x + base + gOf[_ci] + _k0);         \
        }                                                                     \
        cp_commit();                                                          \
    } while (0)

    ISSUE_QK(0, 0);
    ISSUE_QK(1, 32);

    // ---- phase 1: S = G1 @ X^T, warps 4M x 2N; a2 fused ----
    const int wm0 = (wid & 3) * 16, wn0 = (wid >> 2) * 32;
    const int a2r = tid >> 2, a2p = tid & 3;
    float a2acc = 0.f;
    float acc1[4][4] = {};

#pragma unroll
    for (int it = 0; it < 8; it++) {
        const int s = it % 3;
        if (it == 7) cp_wait<0>(); else cp_wait<1>();
        __syncthreads();

        const uint32_t* Qb = Qst + s * QSTG;
        const uint32_t* Kb = Kst + s * QSTG;

#pragma unroll
        for (int j = 0; j < 8; j++) {
            int cl = a2p * 8 + j;
            a2acc += __uint_as_float(Kb[a2r * QS_STRIDE + cl]) * wvs[it * 32 + cl];
        }

#pragma unroll
        for (int ks = 0; ks < 32; ks += 8) {
            uint32_t a[4], b[2][4];
            ldsm4(a, &Qb[(wm0 + lrA) * QS_STRIDE + ks + lkA]);
#pragma unroll
            for (int p = 0; p < 2; p++)
                ldsm4(b[p], &Kb[(wn0 + p * 16 + lrB) * QS_STRIDE + ks + lkB]);
#pragma unroll
            for (int p = 0; p < 2; p++)
#pragma unroll
                for (int j = 0; j < 4; j++) b[p][j] = u2tf(b[p][j]);
#pragma unroll
            for (int nt = 0; nt < 4; nt++) {
                int p = nt >> 1, hi = (nt & 1) * 2;
                mma8(acc1[nt], a[0], a[1], a[2], a[3], b[p][hi], b[p][hi + 1]);
            }
        }
        if (it + 2 < 8) ISSUE_QK((it + 2) % 3, (it + 2) * 32);
    }
#undef ISSUE_QK

    a2acc += __shfl_xor_sync(0xffffffffu, a2acc, 1);
    a2acc += __shfl_xor_sync(0xffffffffu, a2acc, 2);
    if (a2p == 0) a2s[a2r] = a2acc * SCALE;
    __syncthreads();

    // bias + a2 add, stash S (fp32)
    {
        const float* bb = g_bias + (w >> 6) * (NTOK * NTOK);
        float* Sf = (float*)Ss;
#pragma unroll
        for (int nt = 0; nt < 4; nt++) {
            int col = wn0 + nt * 8 + 2 * tg;
            int r0 = wm0 + g;
            float a0 = a2s[col], a1 = a2s[col + 1];
            Sf[r0 * SS_STRIDE + col]           = acc1[nt][0] + bb[r0 * 64 + col]       + a0;
            Sf[r0 * SS_STRIDE + col + 1]       = acc1[nt][1] + bb[r0 * 64 + col + 1]   + a1;
            Sf[(r0 + 8) * SS_STRIDE + col]     = acc1[nt][2] + bb[(r0 + 8) * 64 + col] + a0;
            Sf[(r0 + 8) * SS_STRIDE + col + 1] = acc1[nt][3] + bb[(r0 + 8) * 64 + col + 1] + a1;
        }
    }
    __syncthreads();

    // ---- softmax over keys; P as tf32 ----
    {
        float* Sf = (float*)Ss;
        int r = tid >> 2, p = tid & 3;
        float v[16];
        float mx = -1e30f;
#pragma unroll
        for (int i = 0; i < 16; i++) { v[i] = Sf[r * SS_STRIDE + p + 4 * i]; mx = fmaxf(mx, v[i]); }
        mx = fmaxf(mx, __shfl_xor_sync(0xffffffffu, mx, 1));
        mx = fmaxf(mx, __shfl_xor_sync(0xffffffffu, mx, 2));
        float s = 0.f;
#pragma unroll
        for (int i = 0; i < 16; i++) { v[i] = __expf(v[i] - mx); s += v[i]; }
        s += __shfl_xor_sync(0xffffffffu, s, 1);
        s += __shfl_xor_sync(0xffffffffu, s, 2);
        float inv = 1.0f / s;
#pragma unroll
        for (int i = 0; i < 16; i++) Ss[r * SS_STRIDE + p + 4 * i] = f2tf(v[i] * inv);
    }
    __syncthreads();

    // ---- phase 2: out = P @ Z + d, Z fragments direct from global ----
    {
        const int wn = wid * 32;
        const uint32_t* Zp = (const uint32_t*)g_Z + base;
        float acc2[4][4][4] = {};
#pragma unroll
        for (int ks = 0; ks < 64; ks += 8) {
            uint32_t a[4][4];
#pragma unroll
            for (int mt = 0; mt < 4; mt++)
                ldsm4(a[mt], &Ss[(mt * 16 + lrA) * SS_STRIDE + ks + lkA]);
            uint32_t b0[4], b1[4];
#pragma unroll
            for (int nt = 0; nt < 4; nt++) {
                b0[nt] = Zp[(ks + tg) * 256 + wn + nt * 8 + g];
                b1[nt] = Zp[(ks + tg + 4) * 256 + wn + nt * 8 + g];
            }
#pragma unroll
            for (int nt = 0; nt < 4; nt++)
#pragma unroll
                for (int mt = 0; mt < 4; mt++)
                    mma8(acc2[mt][nt], a[mt][0], a[mt][1], a[mt][2], a[mt][3], b0[nt], b1[nt]);
        }
#pragma unroll
        for (int mt = 0; mt < 4; mt++)
#pragma unroll
            for (int nt = 0; nt < 4; nt++) {
                int col = wn + nt * 8 + 2 * tg, r0 = mt * 16 + g;
                float d0 = g_d[col], d1 = g_d[col + 1];
                float2 v0 = { acc2[mt][nt][0] + d0, acc2[mt][nt][1] + d1 };
                float2 v1 = { acc2[mt][nt][2] + d0, acc2[mt][nt][3] + d1 };
                *(float2*)(out + base + r0 * 256 + col)       = v0;
                *(float2*)(out + base + (r0 + 8) * 256 + col) = v1;
            }
    }
}

// ---------------- launch --------------------------------------------------------
extern "C" void kernel_launch(void* const* d_in, const int* in_sizes, int n_in,
                              void* d_out, int out_size)
{
    const float* x         = (const float*)d_in[0];
    const float* theta_max = (const float*)d_in[1];
    const float* qkv_w     = (const float*)d_in[2];
    const float* qkv_b     = (const float*)d_in[3];
    const float* proj_w    = (const float*)d_in[4];
    const float* proj_b    = (const float*)d_in[5];
    const float* a_p       = (const float*)d_in[6];
    const float* b_p       = (const float*)d_in[7];
    const float* a_r       = (const float*)d_in[8];
    const float* b_r       = (const float*)d_in[9];
    const int*   radius    = (const int*)d_in[10];
    const int*   azimuth   = (const int*)d_in[11];
    float*       out       = (float*)d_out;

    bias_kernel<<<NBATCH * 16, 256>>>(theta_max, a_p, b_p, a_r, b_r, radius, azimuth);
    mat_kernel<<<130, 256>>>(qkv_w, qkv_b, proj_w, proj_b);

    const int gemm_smem = GEMM_SMEM_WORDS * (int)sizeof(uint32_t);
    cudaFuncSetAttribute(gemm_g1z_kernel, cudaFuncAttributeMaxDynamicSharedMemorySize, gemm_smem);
    gemm_g1z_kernel<<<dim3(2, MROWS / 128), 256, gemm_smem>>>(x);

    const int attn_smem = ATTN_SMEM_WORDS * (int)sizeof(uint32_t);
    cudaFuncSetAttribute(attn_kernel, cudaFuncAttributeMaxDynamicSharedMemorySize, attn_smem);
    attn_kernel<<<BWIN, 256, attn_smem>>>(x, out);
}